// round 11
// baseline (speedup 1.0000x reference)
#include <cuda_runtime.h>
#include <cuda_bf16.h>
#include <cstdint>

// Problem constants (reference: N=100000, E=1000000, D=64)
#define MAXN 100000
#define MAXE 1000000
#define DIMF 64

// Scratch (device globals; no allocation allowed)
__device__ float g_agg[MAXN * DIMF];
__device__ float g_h1[MAXN * DIMF];
__device__ float g_h2[MAXN * DIMF];
__device__ int   g_cnt[MAXN];
__device__ int   g_rowptr[MAXN + 1];
__device__ int   g_cursor[MAXN];
__device__ int2  g_edata[MAXE];          // {src, float_bits(w)} grouped by dst
__device__ int   g_bsum[512];

// ---------------------------------------------------------------------------
// TF32 helpers
// ---------------------------------------------------------------------------
__device__ __forceinline__ uint32_t f2tf(float a) {
    uint32_t r; asm("cvt.rna.tf32.f32 %0, %1;" : "=r"(r) : "f"(a)); return r;
}
__device__ __forceinline__ void tf_split(float a, uint32_t& hi, uint32_t& lo) {
    hi = f2tf(a);
    lo = f2tf(a - __uint_as_float(hi));
}
__device__ __forceinline__ void mma_tf32(float c[4],
                                         uint32_t a0, uint32_t a1, uint32_t a2, uint32_t a3,
                                         uint32_t b0, uint32_t b1) {
    asm volatile(
        "mma.sync.aligned.m16n8k8.row.col.f32.tf32.tf32.f32 "
        "{%0,%1,%2,%3}, {%4,%5,%6,%7}, {%8,%9}, {%0,%1,%2,%3};"
        : "+f"(c[0]), "+f"(c[1]), "+f"(c[2]), "+f"(c[3])
        : "r"(a0), "r"(a1), "r"(a2), "r"(a3), "r"(b0), "r"(b1));
}

// ---------------------------------------------------------------------------
// CSR build: histogram -> exclusive scan -> fill
// ---------------------------------------------------------------------------
__global__ void zero_cnt_kernel(int* __restrict__ cnt, int N) {
    int i = blockIdx.x * blockDim.x + threadIdx.x;
    if (i < N) cnt[i] = 0;
}

__global__ void hist_kernel(const int* __restrict__ dst, int* __restrict__ cnt, int E) {
    int e = blockIdx.x * blockDim.x + threadIdx.x;
    if (e < E) atomicAdd(&cnt[dst[e]], 1);
}

__global__ void scan_partial_kernel(const int* __restrict__ cnt, int* __restrict__ bsum, int N) {
    __shared__ int sm[256];
    int i = blockIdx.x * 256 + threadIdx.x;
    sm[threadIdx.x] = (i < N) ? cnt[i] : 0;
    __syncthreads();
    for (int s = 128; s > 0; s >>= 1) {
        if (threadIdx.x < s) sm[threadIdx.x] += sm[threadIdx.x + s];
        __syncthreads();
    }
    if (threadIdx.x == 0) bsum[blockIdx.x] = sm[0];
}

__global__ void scan_top_kernel(int* __restrict__ bsum, int NB) {
    int lane = threadIdx.x;          // 32 threads
    int carry = 0;
    for (int base = 0; base < NB; base += 32) {
        int i = base + lane;
        int v = (i < NB) ? bsum[i] : 0;
        int s = v;
        #pragma unroll
        for (int d = 1; d < 32; d <<= 1) {
            int t = __shfl_up_sync(0xFFFFFFFFu, s, d);
            if (lane >= d) s += t;
        }
        if (i < NB) bsum[i] = carry + s - v;   // exclusive
        carry += __shfl_sync(0xFFFFFFFFu, s, 31);
    }
}

__global__ void scan_final_kernel(const int* __restrict__ cnt,
                                  const int* __restrict__ bsum,
                                  int* __restrict__ rowptr,
                                  int* __restrict__ cursor, int N) {
    __shared__ int sm[256];
    int t = threadIdx.x;
    int i = blockIdx.x * 256 + t;
    int v = (i < N) ? cnt[i] : 0;
    sm[t] = v;
    __syncthreads();
    for (int s = 1; s < 256; s <<= 1) {
        int add = (t >= s) ? sm[t - s] : 0;
        __syncthreads();
        sm[t] += add;
        __syncthreads();
    }
    int val = bsum[blockIdx.x] + sm[t] - v;   // exclusive prefix
    if (i < N) {
        rowptr[i] = val;
        cursor[i] = val;
    } else if (i == N) {
        rowptr[N] = val;                      // == E
    }
}

__global__ void fill_kernel(const int* __restrict__ src, const int* __restrict__ dst,
                            const float* __restrict__ ew,
                            int* __restrict__ cursor, int2* __restrict__ edata, int E) {
    int e = blockIdx.x * blockDim.x + threadIdx.x;
    if (e >= E) return;
    int d = dst[e];
    int p = atomicAdd(&cursor[d], 1);
    edata[p] = make_int2(src[e], __float_as_int(ew[e]));
}

// ---------------------------------------------------------------------------
// Gather-aggregate: agg[n] = x[n] + sum_{e in csr(n)} x[src_e] * w_e
// (unchanged R6/R7 winner)
// ---------------------------------------------------------------------------
__global__ void gather_kernel(const float4* __restrict__ x4,
                              const int* __restrict__ rowptr,
                              const int2* __restrict__ edata,
                              float4* __restrict__ agg, int N) {
    int idx = blockIdx.x * blockDim.x + threadIdx.x;
    int n = idx >> 4;
    if (n >= N) return;
    int c = idx & 15;
    unsigned gmask = 0xFFFFu << (threadIdx.x & 16);   // this 16-lane group

    int beg = __ldg(rowptr + n);
    int end = __ldg(rowptr + n + 1);
    float4 acc = x4[(size_t)n * 16 + c];    // GIN identity term

    for (int base = beg; base < end; base += 16) {
        int e = base + c;
        int2 ed = (e < end) ? __ldg(edata + e) : make_int2(0, 0);
        #pragma unroll
        for (int i = 0; i < 16; i++) {
            int s   = __shfl_sync(gmask, ed.x, i, 16);
            float w = __int_as_float(__shfl_sync(gmask, ed.y, i, 16));
            float4 v = __ldg(&x4[(size_t)s * 16 + c]);
            acc.x += v.x * w; acc.y += v.y * w;
            acc.z += v.z * w; acc.w += v.w * w;
        }
    }
    agg[(size_t)n * 16 + c] = acc;
}

// ---------------------------------------------------------------------------
// Tensor-core MLP (pre-split TF32): out = [relu](relu(agg@W1+b1)@W2+b2)
//
// All hi/lo tf32 splits hoisted OUT of the GEMM loops: staging converts the
// input tile and both weight matrices into paired hi/lo smem arrays; GEMM1
// writes hid as a hi/lo pair (split applied once at write). Inner loops are
// pure LDS+MMA (3 MMAs per tile: Ah*Bh + Ah*Bl + Al*Bh; fp32 accumulate).
// TR=128 rows, 512 threads, 1 block/SM (smem 144KB / 214KB of 228KB).
// Strides: A-side ==4 mod 32 (banks 4g+tg distinct), B-side ==8 mod 32
// (banks 8tg+g distinct) -> all fragment loads conflict-free.
// Warp mapping (16 warps): m-tile = wid>>1 (8 x 16 rows), n-half = wid&1.
// ---------------------------------------------------------------------------
template<int H, bool RELU_OUT>
__global__ void __launch_bounds__(512, 1) mlp_tc_kernel(
        const float4* __restrict__ agg4,
        const float* __restrict__ w1, const float* __restrict__ b1,
        const float* __restrict__ w2, const float* __restrict__ b2,
        float* __restrict__ out, int N) {
    constexpr int TR   = 128;
    constexpr int INS  = 68;        // in stride (floats), ==4 mod 32
    constexpr int W1S  = H + 8;     // w1 stride, ==8 mod 32
    constexpr int HS   = H + 4;     // hid stride, ==4 mod 32
    constexpr int W2S  = 72;        // w2 stride, ==8 mod 32
    constexpr int IN_SZ = TR * INS;            // floats per hi/lo plane
    constexpr int W1_SZ = 64 * W1S;
    constexpr int NT1  = H / 16;    // n-tiles per warp in GEMM1
    constexpr int KS2  = H / 8;     // k-steps in GEMM2

    extern __shared__ float sm[];
    float* in_hi  = sm;                        // [TR][INS]
    float* in_lo  = in_hi + IN_SZ;
    float* w1_hi  = in_lo + IN_SZ;             // [64][W1S]
    float* w1_lo  = w1_hi + W1_SZ;
    float* hid_hi = sm;                        // [TR][HS], overlays in+w1
    float* hid_lo = hid_hi + TR * HS;
    float* w2_hi  = w1_lo + W1_SZ;             // [H][W2S]
    float* w2_lo  = w2_hi + H * W2S;
    float* b1s    = w2_lo + H * W2S;           // H
    float* b2s    = b1s + H;                   // 64
    static_assert(2 * TR * HS <= 2 * IN_SZ + 2 * W1_SZ, "hid overlay must fit");

    int tid  = threadIdx.x;
    int row0 = blockIdx.x * TR;
    int nrows = N - row0; if (nrows > TR) nrows = TR;

    // Stage pre-split weights + biases
    for (int i = tid; i < 64 * H; i += 512) {
        int k = i / H, n = i % H;
        uint32_t hi, lo; tf_split(w1[i], hi, lo);
        w1_hi[k * W1S + n] = __uint_as_float(hi);
        w1_lo[k * W1S + n] = __uint_as_float(lo);
    }
    for (int i = tid; i < H * 64; i += 512) {
        int h = i / 64, n = i % 64;
        uint32_t hi, lo; tf_split(w2[i], hi, lo);
        w2_hi[h * W2S + n] = __uint_as_float(hi);
        w2_lo[h * W2S + n] = __uint_as_float(lo);
    }
    if (tid < H)  b1s[tid] = b1[tid];
    if (tid < 64) b2s[tid] = b2[tid];

    // Stage pre-split input tile (zero-pad tail rows)
    for (int i = tid; i < TR * 16; i += 512) {
        int r = i >> 4, k4 = i & 15;
        float4 v = make_float4(0.f, 0.f, 0.f, 0.f);
        if (r < nrows) v = agg4[(size_t)(row0 + r) * 16 + k4];
        uint32_t h0, l0, h1, l1, h2, l2, h3, l3;
        tf_split(v.x, h0, l0); tf_split(v.y, h1, l1);
        tf_split(v.z, h2, l2); tf_split(v.w, h3, l3);
        *(float4*)(in_hi + r * INS + k4 * 4) = make_float4(
            __uint_as_float(h0), __uint_as_float(h1), __uint_as_float(h2), __uint_as_float(h3));
        *(float4*)(in_lo + r * INS + k4 * 4) = make_float4(
            __uint_as_float(l0), __uint_as_float(l1), __uint_as_float(l2), __uint_as_float(l3));
    }
    __syncthreads();

    const int wid  = tid >> 5;
    const int lane = tid & 31;
    const int g    = lane >> 2;     // groupID (row within tile)
    const int tg   = lane & 3;      // thread-in-group (col)
    const int m0   = (wid >> 1) * 16;
    const int nb1  = (wid & 1) * NT1 * 8;   // GEMM1 n-tile base

    // ---- GEMM1: hid = relu(in @ W1 + b1) ----
    float c1[NT1][4];
    #pragma unroll
    for (int j = 0; j < NT1; j++) {
        int n0 = nb1 + j * 8;
        float bv0 = b1s[n0 + 2 * tg], bv1 = b1s[n0 + 2 * tg + 1];
        c1[j][0] = bv0; c1[j][1] = bv1; c1[j][2] = bv0; c1[j][3] = bv1;
    }
    #pragma unroll
    for (int kk = 0; kk < 8; kk++) {        // K = 64
        int k0 = kk * 8;
        uint32_t ah[4], al[4];
        ah[0] = __float_as_uint(in_hi[(m0 + g)     * INS + k0 + tg]);
        ah[1] = __float_as_uint(in_hi[(m0 + g + 8) * INS + k0 + tg]);
        ah[2] = __float_as_uint(in_hi[(m0 + g)     * INS + k0 + tg + 4]);
        ah[3] = __float_as_uint(in_hi[(m0 + g + 8) * INS + k0 + tg + 4]);
        al[0] = __float_as_uint(in_lo[(m0 + g)     * INS + k0 + tg]);
        al[1] = __float_as_uint(in_lo[(m0 + g + 8) * INS + k0 + tg]);
        al[2] = __float_as_uint(in_lo[(m0 + g)     * INS + k0 + tg + 4]);
        al[3] = __float_as_uint(in_lo[(m0 + g + 8) * INS + k0 + tg + 4]);
        #pragma unroll
        for (int j = 0; j < NT1; j++) {
            int n0 = nb1 + j * 8;
            uint32_t bh0 = __float_as_uint(w1_hi[(k0 + tg)     * W1S + n0 + g]);
            uint32_t bh1 = __float_as_uint(w1_hi[(k0 + tg + 4) * W1S + n0 + g]);
            uint32_t bl0 = __float_as_uint(w1_lo[(k0 + tg)     * W1S + n0 + g]);
            uint32_t bl1 = __float_as_uint(w1_lo[(k0 + tg + 4) * W1S + n0 + g]);
            mma_tf32(c1[j], ah[0], ah[1], ah[2], ah[3], bh0, bh1);
            mma_tf32(c1[j], ah[0], ah[1], ah[2], ah[3], bl0, bl1);
            mma_tf32(c1[j], al[0], al[1], al[2], al[3], bh0, bh1);
        }
    }
    __syncthreads();   // all reads of in/w1 planes done

    // Write relu(hid) as pre-split hi/lo pair (overlays in+w1 region)
    #pragma unroll
    for (int j = 0; j < NT1; j++) {
        int n0 = nb1 + j * 8 + 2 * tg;
        #pragma unroll
        for (int half = 0; half < 2; half++) {
            int r = m0 + g + 8 * half;
            float v0 = fmaxf(c1[j][2 * half],     0.f);
            float v1 = fmaxf(c1[j][2 * half + 1], 0.f);
            uint32_t h0, l0, h1, l1;
            tf_split(v0, h0, l0); tf_split(v1, h1, l1);
            *(float2*)(hid_hi + r * HS + n0) =
                make_float2(__uint_as_float(h0), __uint_as_float(h1));
            *(float2*)(hid_lo + r * HS + n0) =
                make_float2(__uint_as_float(l0), __uint_as_float(l1));
        }
    }
    __syncthreads();

    // ---- GEMM2: out = hid @ W2 + b2 ----
    {
        constexpr int NT2 = 4;               // 8 n-tiles, 2 warps per m
        int nb2 = (wid & 1) * 32;
        float c2[NT2][4];
        #pragma unroll
        for (int j = 0; j < NT2; j++) {
            int n0 = nb2 + j * 8;
            float bv0 = b2s[n0 + 2 * tg], bv1 = b2s[n0 + 2 * tg + 1];
            c2[j][0] = bv0; c2[j][1] = bv1; c2[j][2] = bv0; c2[j][3] = bv1;
        }
        #pragma unroll
        for (int kk = 0; kk < KS2; kk++) {
            int k0 = kk * 8;
            uint32_t ah[4], al[4];
            ah[0] = __float_as_uint(hid_hi[(m0 + g)     * HS + k0 + tg]);
            ah[1] = __float_as_uint(hid_hi[(m0 + g + 8) * HS + k0 + tg]);
            ah[2] = __float_as_uint(hid_hi[(m0 + g)     * HS + k0 + tg + 4]);
            ah[3] = __float_as_uint(hid_hi[(m0 + g + 8) * HS + k0 + tg + 4]);
            al[0] = __float_as_uint(hid_lo[(m0 + g)     * HS + k0 + tg]);
            al[1] = __float_as_uint(hid_lo[(m0 + g + 8) * HS + k0 + tg]);
            al[2] = __float_as_uint(hid_lo[(m0 + g)     * HS + k0 + tg + 4]);
            al[3] = __float_as_uint(hid_lo[(m0 + g + 8) * HS + k0 + tg + 4]);
            #pragma unroll
            for (int j = 0; j < NT2; j++) {
                int n0 = nb2 + j * 8;
                uint32_t bh0 = __float_as_uint(w2_hi[(k0 + tg)     * W2S + n0 + g]);
                uint32_t bh1 = __float_as_uint(w2_hi[(k0 + tg + 4) * W2S + n0 + g]);
                uint32_t bl0 = __float_as_uint(w2_lo[(k0 + tg)     * W2S + n0 + g]);
                uint32_t bl1 = __float_as_uint(w2_lo[(k0 + tg + 4) * W2S + n0 + g]);
                mma_tf32(c2[j], ah[0], ah[1], ah[2], ah[3], bh0, bh1);
                mma_tf32(c2[j], ah[0], ah[1], ah[2], ah[3], bl0, bl1);
                mma_tf32(c2[j], al[0], al[1], al[2], al[3], bh0, bh1);
            }
        }
        // Write output (float2 per row-fragment, guarded)
        int r0 = m0 + g, r1 = m0 + g + 8;
        #pragma unroll
        for (int j = 0; j < NT2; j++) {
            int n0 = nb2 + j * 8 + 2 * tg;
            if (r0 < nrows) {
                float2 v = make_float2(c2[j][0], c2[j][1]);
                if (RELU_OUT) { v.x = fmaxf(v.x, 0.f); v.y = fmaxf(v.y, 0.f); }
                *(float2*)(out + (size_t)(row0 + r0) * 64 + n0) = v;
            }
            if (r1 < nrows) {
                float2 v = make_float2(c2[j][2], c2[j][3]);
                if (RELU_OUT) { v.x = fmaxf(v.x, 0.f); v.y = fmaxf(v.y, 0.f); }
                *(float2*)(out + (size_t)(row0 + r1) * 64 + n0) = v;
            }
        }
    }
}

// ---------------------------------------------------------------------------
// Launch
// ---------------------------------------------------------------------------
static inline size_t mlp_smem(int H) {
    size_t floats = (size_t)2 * 128 * 68           // in hi/lo
                  + (size_t)2 * 64 * (H + 8)       // w1 hi/lo
                  + (size_t)2 * H * 72             // w2 hi/lo
                  + H + 64;                        // biases
    return floats * sizeof(float);
}

extern "C" void kernel_launch(void* const* d_in, const int* in_sizes, int n_in,
                              void* d_out, int out_size) {
    const float* x   = (const float*)d_in[0];
    const int*   ei  = (const int*)d_in[1];
    const float* ew  = (const float*)d_in[2];
    const float* w11 = (const float*)d_in[3];
    const float* b11 = (const float*)d_in[4];
    const float* w12 = (const float*)d_in[5];
    const float* b12 = (const float*)d_in[6];
    const float* w21 = (const float*)d_in[7];
    const float* b21 = (const float*)d_in[8];
    const float* w22 = (const float*)d_in[9];
    const float* b22 = (const float*)d_in[10];
    const float* w31 = (const float*)d_in[11];
    const float* b31 = (const float*)d_in[12];
    const float* w32 = (const float*)d_in[13];
    const float* b32 = (const float*)d_in[14];
    float* out = (float*)d_out;

    int N = in_sizes[0] / DIMF;
    int E = in_sizes[1] / 2;
    const int* src = ei;
    const int* dst = ei + E;

    float *agg, *h1, *h2;
    int *cnt, *rowptr, *cursor, *bsum;
    int2 *edata;
    cudaGetSymbolAddress((void**)&agg, g_agg);
    cudaGetSymbolAddress((void**)&h1, g_h1);
    cudaGetSymbolAddress((void**)&h2, g_h2);
    cudaGetSymbolAddress((void**)&cnt, g_cnt);
    cudaGetSymbolAddress((void**)&rowptr, g_rowptr);
    cudaGetSymbolAddress((void**)&cursor, g_cursor);
    cudaGetSymbolAddress((void**)&bsum, g_bsum);
    cudaGetSymbolAddress((void**)&edata, g_edata);

    size_t sm64  = mlp_smem(64);
    size_t sm128 = mlp_smem(128);
    cudaFuncSetAttribute(mlp_tc_kernel<64, true>,  cudaFuncAttributeMaxDynamicSharedMemorySize, (int)sm64);
    cudaFuncSetAttribute(mlp_tc_kernel<128, true>, cudaFuncAttributeMaxDynamicSharedMemorySize, (int)sm128);
    cudaFuncSetAttribute(mlp_tc_kernel<64, false>, cudaFuncAttributeMaxDynamicSharedMemorySize, (int)sm64);

    int NB = (N + 255) / 256;                // scan blocks (<=512 required)
    int eb = (E + 255) / 256;
    int gb = (N * 16 + 255) / 256;
    int mb = (N + 127) / 128;

    // --- CSR build (by destination) ---
    zero_cnt_kernel<<<NB, 256>>>(cnt, N);
    hist_kernel<<<eb, 256>>>(dst, cnt, E);
    scan_partial_kernel<<<NB, 256>>>(cnt, bsum, N);
    scan_top_kernel<<<1, 32>>>(bsum, NB);
    scan_final_kernel<<<NB + 1, 256>>>(cnt, bsum, rowptr, cursor, N);
    fill_kernel<<<eb, 256>>>(src, dst, ew, cursor, edata, E);

    // --- Layer 1: 64 -> 64 -> 64, relu ---
    gather_kernel<<<gb, 256>>>((const float4*)x, rowptr, edata, (float4*)agg, N);
    mlp_tc_kernel<64, true><<<mb, 512, sm64>>>((const float4*)agg, w11, b11, w12, b12, h1, N);

    // --- Layer 2: 64 -> 128 -> 64, relu ---
    gather_kernel<<<gb, 256>>>((const float4*)h1, rowptr, edata, (float4*)agg, N);
    mlp_tc_kernel<128, true><<<mb, 512, sm128>>>((const float4*)agg, w21, b21, w22, b22, h2, N);

    // --- Layer 3: 64 -> 64 -> 64, no relu ---
    gather_kernel<<<gb, 256>>>((const float4*)h2, rowptr, edata, (float4*)agg, N);
    mlp_tc_kernel<64, false><<<mb, 512, sm64>>>((const float4*)agg, w31, b31, w32, b32, out, N);
}

// round 12
// speedup vs baseline: 1.0770x; 1.0770x over previous
#include <cuda_runtime.h>
#include <cuda_bf16.h>
#include <cstdint>

// Problem constants (reference: N=100000, E=1000000, D=64)
#define MAXN 100000
#define MAXE 1000000
#define DIMF 64

// Scratch (device globals; no allocation allowed)
__device__ float g_agg[MAXN * DIMF];
__device__ float g_h1[MAXN * DIMF];
__device__ float g_h2[MAXN * DIMF];
__device__ int   g_cnt[MAXN];
__device__ int   g_rowptr[MAXN + 1];
__device__ int   g_cursor[MAXN];
__device__ int2  g_edata[MAXE];          // {src, float_bits(w)} grouped by dst
__device__ int   g_bsum[512];

// ---------------------------------------------------------------------------
// TF32 helpers
// ---------------------------------------------------------------------------
__device__ __forceinline__ uint32_t f2tf(float a) {
    uint32_t r; asm("cvt.rna.tf32.f32 %0, %1;" : "=r"(r) : "f"(a)); return r;
}
__device__ __forceinline__ void tf_split(float a, uint32_t& hi, uint32_t& lo) {
    hi = f2tf(a);
    lo = f2tf(a - __uint_as_float(hi));
}
__device__ __forceinline__ void mma_tf32(float c[4],
                                         uint32_t a0, uint32_t a1, uint32_t a2, uint32_t a3,
                                         uint32_t b0, uint32_t b1) {
    asm volatile(
        "mma.sync.aligned.m16n8k8.row.col.f32.tf32.tf32.f32 "
        "{%0,%1,%2,%3}, {%4,%5,%6,%7}, {%8,%9}, {%0,%1,%2,%3};"
        : "+f"(c[0]), "+f"(c[1]), "+f"(c[2]), "+f"(c[3])
        : "r"(a0), "r"(a1), "r"(a2), "r"(a3), "r"(b0), "r"(b1));
}

// ---------------------------------------------------------------------------
// CSR build: histogram -> exclusive scan -> fill
// ---------------------------------------------------------------------------
__global__ void zero_cnt_kernel(int* __restrict__ cnt, int N) {
    int i = blockIdx.x * blockDim.x + threadIdx.x;
    if (i < N) cnt[i] = 0;
}

__global__ void hist_kernel(const int* __restrict__ dst, int* __restrict__ cnt, int E) {
    int e = blockIdx.x * blockDim.x + threadIdx.x;
    if (e < E) atomicAdd(&cnt[dst[e]], 1);
}

__global__ void scan_partial_kernel(const int* __restrict__ cnt, int* __restrict__ bsum, int N) {
    __shared__ int sm[256];
    int i = blockIdx.x * 256 + threadIdx.x;
    sm[threadIdx.x] = (i < N) ? cnt[i] : 0;
    __syncthreads();
    for (int s = 128; s > 0; s >>= 1) {
        if (threadIdx.x < s) sm[threadIdx.x] += sm[threadIdx.x + s];
        __syncthreads();
    }
    if (threadIdx.x == 0) bsum[blockIdx.x] = sm[0];
}

__global__ void scan_top_kernel(int* __restrict__ bsum, int NB) {
    int lane = threadIdx.x;          // 32 threads
    int carry = 0;
    for (int base = 0; base < NB; base += 32) {
        int i = base + lane;
        int v = (i < NB) ? bsum[i] : 0;
        int s = v;
        #pragma unroll
        for (int d = 1; d < 32; d <<= 1) {
            int t = __shfl_up_sync(0xFFFFFFFFu, s, d);
            if (lane >= d) s += t;
        }
        if (i < NB) bsum[i] = carry + s - v;   // exclusive
        carry += __shfl_sync(0xFFFFFFFFu, s, 31);
    }
}

__global__ void scan_final_kernel(const int* __restrict__ cnt,
                                  const int* __restrict__ bsum,
                                  int* __restrict__ rowptr,
                                  int* __restrict__ cursor, int N) {
    __shared__ int sm[256];
    int t = threadIdx.x;
    int i = blockIdx.x * 256 + t;
    int v = (i < N) ? cnt[i] : 0;
    sm[t] = v;
    __syncthreads();
    for (int s = 1; s < 256; s <<= 1) {
        int add = (t >= s) ? sm[t - s] : 0;
        __syncthreads();
        sm[t] += add;
        __syncthreads();
    }
    int val = bsum[blockIdx.x] + sm[t] - v;   // exclusive prefix
    if (i < N) {
        rowptr[i] = val;
        cursor[i] = val;
    } else if (i == N) {
        rowptr[N] = val;                      // == E
    }
}

__global__ void fill_kernel(const int* __restrict__ src, const int* __restrict__ dst,
                            const float* __restrict__ ew,
                            int* __restrict__ cursor, int2* __restrict__ edata, int E) {
    int e = blockIdx.x * blockDim.x + threadIdx.x;
    if (e >= E) return;
    int d = dst[e];
    int p = atomicAdd(&cursor[d], 1);
    edata[p] = make_int2(src[e], __float_as_int(ew[e]));
}

// ---------------------------------------------------------------------------
// Gather-aggregate: agg[n] = x[n] + sum_{e in csr(n)} x[src_e] * w_e
// (unchanged R6/R7 winner)
// ---------------------------------------------------------------------------
__global__ void gather_kernel(const float4* __restrict__ x4,
                              const int* __restrict__ rowptr,
                              const int2* __restrict__ edata,
                              float4* __restrict__ agg, int N) {
    int idx = blockIdx.x * blockDim.x + threadIdx.x;
    int n = idx >> 4;
    if (n >= N) return;
    int c = idx & 15;
    unsigned gmask = 0xFFFFu << (threadIdx.x & 16);   // this 16-lane group

    int beg = __ldg(rowptr + n);
    int end = __ldg(rowptr + n + 1);
    float4 acc = x4[(size_t)n * 16 + c];    // GIN identity term

    for (int base = beg; base < end; base += 16) {
        int e = base + c;
        int2 ed = (e < end) ? __ldg(edata + e) : make_int2(0, 0);
        #pragma unroll
        for (int i = 0; i < 16; i++) {
            int s   = __shfl_sync(gmask, ed.x, i, 16);
            float w = __int_as_float(__shfl_sync(gmask, ed.y, i, 16));
            float4 v = __ldg(&x4[(size_t)s * 16 + c]);
            acc.x += v.x * w; acc.y += v.y * w;
            acc.z += v.z * w; acc.w += v.w * w;
        }
    }
    agg[(size_t)n * 16 + c] = acc;
}

// ---------------------------------------------------------------------------
// Pre-split TF32 MLP for H=64 (TR=64, 256 threads, 2 blocks/SM; smem 109KB).
// All hi/lo splits hoisted to staging; inner loops pure LDS+MMA.
// Strides: A-side (in/hid) 68 ==4 mod 32; B-side (w1/w2) 72 ==8 mod 32.
// hid hi/lo overlays the in hi/lo planes after GEMM1.
// ---------------------------------------------------------------------------
template<bool RELU_OUT>
__global__ void __launch_bounds__(256, 2) mlp_tc64_kernel(
        const float4* __restrict__ agg4,
        const float* __restrict__ w1, const float* __restrict__ b1,
        const float* __restrict__ w2, const float* __restrict__ b2,
        float* __restrict__ out, int N) {
    constexpr int TR  = 64;
    constexpr int INS = 68;         // ==4 mod 32
    constexpr int WS  = 72;         // ==8 mod 32 (both w1 and w2, H=64)
    constexpr int IN_SZ = TR * INS; // 4352 floats per plane
    constexpr int W_SZ  = 64 * WS;  // 4608 floats per plane

    extern __shared__ float sm[];
    float* in_hi  = sm;                         // [64][68]
    float* in_lo  = in_hi + IN_SZ;
    float* w1_hi  = in_lo + IN_SZ;              // [64][72]
    float* w1_lo  = w1_hi + W_SZ;
    float* hid_hi = sm;                         // overlays in_hi
    float* hid_lo = in_lo;                      // overlays in_lo
    float* w2_hi  = w1_lo + W_SZ;
    float* w2_lo  = w2_hi + W_SZ;
    float* b1s    = w2_lo + W_SZ;               // 64
    float* b2s    = b1s + 64;                   // 64

    int tid  = threadIdx.x;
    int row0 = blockIdx.x * TR;
    int nrows = N - row0; if (nrows > TR) nrows = TR;

    // Stage pre-split weights + biases
    for (int i = tid; i < 64 * 64; i += 256) {
        int k = i >> 6, n = i & 63;
        uint32_t hi, lo; tf_split(w1[i], hi, lo);
        w1_hi[k * WS + n] = __uint_as_float(hi);
        w1_lo[k * WS + n] = __uint_as_float(lo);
        uint32_t hi2, lo2; tf_split(w2[i], hi2, lo2);
        w2_hi[k * WS + n] = __uint_as_float(hi2);
        w2_lo[k * WS + n] = __uint_as_float(lo2);
    }
    if (tid < 64)  b1s[tid] = b1[tid];
    else if (tid < 128) b2s[tid - 64] = b2[tid - 64];

    // Stage pre-split input tile (zero-pad tail rows)
    for (int i = tid; i < TR * 16; i += 256) {
        int r = i >> 4, k4 = i & 15;
        float4 v = make_float4(0.f, 0.f, 0.f, 0.f);
        if (r < nrows) v = agg4[(size_t)(row0 + r) * 16 + k4];
        uint32_t h0, l0, h1, l1, h2, l2, h3, l3;
        tf_split(v.x, h0, l0); tf_split(v.y, h1, l1);
        tf_split(v.z, h2, l2); tf_split(v.w, h3, l3);
        *(float4*)(in_hi + r * INS + k4 * 4) = make_float4(
            __uint_as_float(h0), __uint_as_float(h1), __uint_as_float(h2), __uint_as_float(h3));
        *(float4*)(in_lo + r * INS + k4 * 4) = make_float4(
            __uint_as_float(l0), __uint_as_float(l1), __uint_as_float(l2), __uint_as_float(l3));
    }
    __syncthreads();

    const int wid  = tid >> 5;
    const int lane = tid & 31;
    const int g    = lane >> 2;
    const int tg   = lane & 3;
    const int m0   = (wid >> 1) * 16;
    const int nb   = (wid & 1) * 32;    // n-half base (4 tiles of 8)

    // ---- GEMM1: hid = relu(in @ W1 + b1) ----
    float c1[4][4];
    #pragma unroll
    for (int j = 0; j < 4; j++) {
        int n0 = nb + j * 8;
        float bv0 = b1s[n0 + 2 * tg], bv1 = b1s[n0 + 2 * tg + 1];
        c1[j][0] = bv0; c1[j][1] = bv1; c1[j][2] = bv0; c1[j][3] = bv1;
    }
    #pragma unroll
    for (int kk = 0; kk < 8; kk++) {
        int k0 = kk * 8;
        uint32_t ah[4], al[4];
        ah[0] = __float_as_uint(in_hi[(m0 + g)     * INS + k0 + tg]);
        ah[1] = __float_as_uint(in_hi[(m0 + g + 8) * INS + k0 + tg]);
        ah[2] = __float_as_uint(in_hi[(m0 + g)     * INS + k0 + tg + 4]);
        ah[3] = __float_as_uint(in_hi[(m0 + g + 8) * INS + k0 + tg + 4]);
        al[0] = __float_as_uint(in_lo[(m0 + g)     * INS + k0 + tg]);
        al[1] = __float_as_uint(in_lo[(m0 + g + 8) * INS + k0 + tg]);
        al[2] = __float_as_uint(in_lo[(m0 + g)     * INS + k0 + tg + 4]);
        al[3] = __float_as_uint(in_lo[(m0 + g + 8) * INS + k0 + tg + 4]);
        #pragma unroll
        for (int j = 0; j < 4; j++) {
            int n0 = nb + j * 8;
            uint32_t bh0 = __float_as_uint(w1_hi[(k0 + tg)     * WS + n0 + g]);
            uint32_t bh1 = __float_as_uint(w1_hi[(k0 + tg + 4) * WS + n0 + g]);
            uint32_t bl0 = __float_as_uint(w1_lo[(k0 + tg)     * WS + n0 + g]);
            uint32_t bl1 = __float_as_uint(w1_lo[(k0 + tg + 4) * WS + n0 + g]);
            mma_tf32(c1[j], ah[0], ah[1], ah[2], ah[3], bh0, bh1);
            mma_tf32(c1[j], ah[0], ah[1], ah[2], ah[3], bl0, bl1);
            mma_tf32(c1[j], al[0], al[1], al[2], al[3], bh0, bh1);
        }
    }
    __syncthreads();

    // Write relu(hid) pre-split (overlays in planes)
    #pragma unroll
    for (int j = 0; j < 4; j++) {
        int n0 = nb + j * 8 + 2 * tg;
        #pragma unroll
        for (int half = 0; half < 2; half++) {
            int r = m0 + g + 8 * half;
            float v0 = fmaxf(c1[j][2 * half],     0.f);
            float v1 = fmaxf(c1[j][2 * half + 1], 0.f);
            uint32_t h0, l0, h1, l1;
            tf_split(v0, h0, l0); tf_split(v1, h1, l1);
            *(float2*)(hid_hi + r * INS + n0) =
                make_float2(__uint_as_float(h0), __uint_as_float(h1));
            *(float2*)(hid_lo + r * INS + n0) =
                make_float2(__uint_as_float(l0), __uint_as_float(l1));
        }
    }
    __syncthreads();

    // ---- GEMM2: out = hid @ W2 + b2 ----
    {
        float c2[4][4];
        #pragma unroll
        for (int j = 0; j < 4; j++) {
            int n0 = nb + j * 8;
            float bv0 = b2s[n0 + 2 * tg], bv1 = b2s[n0 + 2 * tg + 1];
            c2[j][0] = bv0; c2[j][1] = bv1; c2[j][2] = bv0; c2[j][3] = bv1;
        }
        #pragma unroll
        for (int kk = 0; kk < 8; kk++) {
            int k0 = kk * 8;
            uint32_t ah[4], al[4];
            ah[0] = __float_as_uint(hid_hi[(m0 + g)     * INS + k0 + tg]);
            ah[1] = __float_as_uint(hid_hi[(m0 + g + 8) * INS + k0 + tg]);
            ah[2] = __float_as_uint(hid_hi[(m0 + g)     * INS + k0 + tg + 4]);
            ah[3] = __float_as_uint(hid_hi[(m0 + g + 8) * INS + k0 + tg + 4]);
            al[0] = __float_as_uint(hid_lo[(m0 + g)     * INS + k0 + tg]);
            al[1] = __float_as_uint(hid_lo[(m0 + g + 8) * INS + k0 + tg]);
            al[2] = __float_as_uint(hid_lo[(m0 + g)     * INS + k0 + tg + 4]);
            al[3] = __float_as_uint(hid_lo[(m0 + g + 8) * INS + k0 + tg + 4]);
            #pragma unroll
            for (int j = 0; j < 4; j++) {
                int n0 = nb + j * 8;
                uint32_t bh0 = __float_as_uint(w2_hi[(k0 + tg)     * WS + n0 + g]);
                uint32_t bh1 = __float_as_uint(w2_hi[(k0 + tg + 4) * WS + n0 + g]);
                uint32_t bl0 = __float_as_uint(w2_lo[(k0 + tg)     * WS + n0 + g]);
                uint32_t bl1 = __float_as_uint(w2_lo[(k0 + tg + 4) * WS + n0 + g]);
                mma_tf32(c2[j], ah[0], ah[1], ah[2], ah[3], bh0, bh1);
                mma_tf32(c2[j], ah[0], ah[1], ah[2], ah[3], bl0, bl1);
                mma_tf32(c2[j], al[0], al[1], al[2], al[3], bh0, bh1);
            }
        }
        int r0 = m0 + g, r1 = m0 + g + 8;
        #pragma unroll
        for (int j = 0; j < 4; j++) {
            int n0 = nb + j * 8 + 2 * tg;
            if (r0 < nrows) {
                float2 v = make_float2(c2[j][0], c2[j][1]);
                if (RELU_OUT) { v.x = fmaxf(v.x, 0.f); v.y = fmaxf(v.y, 0.f); }
                *(float2*)(out + (size_t)(row0 + r0) * 64 + n0) = v;
            }
            if (r1 < nrows) {
                float2 v = make_float2(c2[j][2], c2[j][3]);
                if (RELU_OUT) { v.x = fmaxf(v.x, 0.f); v.y = fmaxf(v.y, 0.f); }
                *(float2*)(out + (size_t)(row0 + r1) * 64 + n0) = v;
            }
        }
    }
}

// ---------------------------------------------------------------------------
// On-the-fly split TF32 MLP (R10 winner) -- used for H=128 (smem 90KB,
// 2 blocks/SM; pre-split would not fit 2 blocks at H=128).
// ---------------------------------------------------------------------------
template<int H, bool RELU_OUT>
__global__ void __launch_bounds__(256, 2) mlp_tc_kernel(
        const float4* __restrict__ agg4,
        const float* __restrict__ w1, const float* __restrict__ b1,
        const float* __restrict__ w2, const float* __restrict__ b2,
        float* __restrict__ out, int N) {
    constexpr int TR   = 64;
    constexpr int INS  = 68;
    constexpr int W1S  = H + 8;
    constexpr int HS   = H + 4;
    constexpr int W2S  = 72;
    constexpr int IN_SZ = TR * INS;
    constexpr int W1_SZ = 64 * W1S;
    constexpr int NT1  = H / 16;
    constexpr int KS2  = H / 8;

    extern __shared__ float sm[];
    float* in_s = sm;
    float* w1n  = sm + IN_SZ;
    float* hid  = sm;
    float* w2n  = sm + IN_SZ + W1_SZ;
    float* b1s  = w2n + H * W2S;
    float* b2s  = b1s + H;
    static_assert(TR * HS <= IN_SZ + W1_SZ, "hid overlay must fit");

    int tid  = threadIdx.x;
    int row0 = blockIdx.x * TR;
    int nrows = N - row0; if (nrows > TR) nrows = TR;

    for (int i = tid; i < 64 * H; i += 256) {
        int k = i / H, n = i % H;
        w1n[k * W1S + n] = w1[i];
    }
    for (int i = tid; i < H * 64; i += 256) {
        int h = i / 64, n = i % 64;
        w2n[h * W2S + n] = w2[i];
    }
    if (tid < H)  b1s[tid] = b1[tid];
    if (tid < 64) b2s[tid] = b2[tid];

    for (int i = tid; i < TR * 16; i += 256) {
        int r = i >> 4, k4 = i & 15;
        float4 v = make_float4(0.f, 0.f, 0.f, 0.f);
        if (r < nrows) v = agg4[(size_t)(row0 + r) * 16 + k4];
        *(float4*)(in_s + r * INS + k4 * 4) = v;
    }
    __syncthreads();

    const int wid  = tid >> 5;
    const int lane = tid & 31;
    const int g    = lane >> 2;
    const int tg   = lane & 3;
    const int m0   = (wid >> 1) * 16;
    const int nb1  = (wid & 1) * NT1 * 8;

    float c1[NT1][4];
    #pragma unroll
    for (int j = 0; j < NT1; j++) {
        int n0 = nb1 + j * 8;
        float bv0 = b1s[n0 + 2 * tg], bv1 = b1s[n0 + 2 * tg + 1];
        c1[j][0] = bv0; c1[j][1] = bv1; c1[j][2] = bv0; c1[j][3] = bv1;
    }
    #pragma unroll
    for (int kk = 0; kk < 8; kk++) {
        int k0 = kk * 8;
        uint32_t ah[4], al[4];
        tf_split(in_s[(m0 + g)     * INS + k0 + tg],     ah[0], al[0]);
        tf_split(in_s[(m0 + g + 8) * INS + k0 + tg],     ah[1], al[1]);
        tf_split(in_s[(m0 + g)     * INS + k0 + tg + 4], ah[2], al[2]);
        tf_split(in_s[(m0 + g + 8) * INS + k0 + tg + 4], ah[3], al[3]);
        #pragma unroll
        for (int j = 0; j < NT1; j++) {
            int n0 = nb1 + j * 8;
            uint32_t bh0, bl0, bh1, bl1;
            tf_split(w1n[(k0 + tg)     * W1S + n0 + g], bh0, bl0);
            tf_split(w1n[(k0 + tg + 4) * W1S + n0 + g], bh1, bl1);
            mma_tf32(c1[j], ah[0], ah[1], ah[2], ah[3], bh0, bh1);
            mma_tf32(c1[j], ah[0], ah[1], ah[2], ah[3], bl0, bl1);
            mma_tf32(c1[j], al[0], al[1], al[2], al[3], bh0, bh1);
        }
    }
    __syncthreads();

    #pragma unroll
    for (int j = 0; j < NT1; j++) {
        int n0 = nb1 + j * 8 + 2 * tg;
        *(float2*)(hid + (m0 + g)     * HS + n0) =
            make_float2(fmaxf(c1[j][0], 0.f), fmaxf(c1[j][1], 0.f));
        *(float2*)(hid + (m0 + g + 8) * HS + n0) =
            make_float2(fmaxf(c1[j][2], 0.f), fmaxf(c1[j][3], 0.f));
    }
    __syncthreads();

    {
        constexpr int NT2 = 4;
        int nb2 = (wid & 1) * 32;
        float c2[NT2][4];
        #pragma unroll
        for (int j = 0; j < NT2; j++) {
            int n0 = nb2 + j * 8;
            float bv0 = b2s[n0 + 2 * tg], bv1 = b2s[n0 + 2 * tg + 1];
            c2[j][0] = bv0; c2[j][1] = bv1; c2[j][2] = bv0; c2[j][3] = bv1;
        }
        #pragma unroll
        for (int kk = 0; kk < KS2; kk++) {
            int k0 = kk * 8;
            uint32_t ah[4], al[4];
            tf_split(hid[(m0 + g)     * HS + k0 + tg],     ah[0], al[0]);
            tf_split(hid[(m0 + g + 8) * HS + k0 + tg],     ah[1], al[1]);
            tf_split(hid[(m0 + g)     * HS + k0 + tg + 4], ah[2], al[2]);
            tf_split(hid[(m0 + g + 8) * HS + k0 + tg + 4], ah[3], al[3]);
            #pragma unroll
            for (int j = 0; j < NT2; j++) {
                int n0 = nb2 + j * 8;
                uint32_t bh0, bl0, bh1, bl1;
                tf_split(w2n[(k0 + tg)     * W2S + n0 + g], bh0, bl0);
                tf_split(w2n[(k0 + tg + 4) * W2S + n0 + g], bh1, bl1);
                mma_tf32(c2[j], ah[0], ah[1], ah[2], ah[3], bh0, bh1);
                mma_tf32(c2[j], ah[0], ah[1], ah[2], ah[3], bl0, bl1);
                mma_tf32(c2[j], al[0], al[1], al[2], al[3], bh0, bh1);
            }
        }
        int r0 = m0 + g, r1 = m0 + g + 8;
        #pragma unroll
        for (int j = 0; j < NT2; j++) {
            int n0 = nb2 + j * 8 + 2 * tg;
            if (r0 < nrows) {
                float2 v = make_float2(c2[j][0], c2[j][1]);
                if (RELU_OUT) { v.x = fmaxf(v.x, 0.f); v.y = fmaxf(v.y, 0.f); }
                *(float2*)(out + (size_t)(row0 + r0) * 64 + n0) = v;
            }
            if (r1 < nrows) {
                float2 v = make_float2(c2[j][2], c2[j][3]);
                if (RELU_OUT) { v.x = fmaxf(v.x, 0.f); v.y = fmaxf(v.y, 0.f); }
                *(float2*)(out + (size_t)(row0 + r1) * 64 + n0) = v;
            }
        }
    }
}

// ---------------------------------------------------------------------------
// Launch
// ---------------------------------------------------------------------------
static inline size_t smem_presplit64() {
    // 2*in(64*68) + 4*w(64*72) + 128 biases
    return (size_t)(2 * 64 * 68 + 4 * 64 * 72 + 128) * sizeof(float);
}
static inline size_t smem_otf(int H) {
    size_t floats = (size_t)64 * 68 + (size_t)64 * (H + 8) + (size_t)H * 72 + H + 64;
    return floats * sizeof(float);
}

extern "C" void kernel_launch(void* const* d_in, const int* in_sizes, int n_in,
                              void* d_out, int out_size) {
    const float* x   = (const float*)d_in[0];
    const int*   ei  = (const int*)d_in[1];
    const float* ew  = (const float*)d_in[2];
    const float* w11 = (const float*)d_in[3];
    const float* b11 = (const float*)d_in[4];
    const float* w12 = (const float*)d_in[5];
    const float* b12 = (const float*)d_in[6];
    const float* w21 = (const float*)d_in[7];
    const float* b21 = (const float*)d_in[8];
    const float* w22 = (const float*)d_in[9];
    const float* b22 = (const float*)d_in[10];
    const float* w31 = (const float*)d_in[11];
    const float* b31 = (const float*)d_in[12];
    const float* w32 = (const float*)d_in[13];
    const float* b32 = (const float*)d_in[14];
    float* out = (float*)d_out;

    int N = in_sizes[0] / DIMF;
    int E = in_sizes[1] / 2;
    const int* src = ei;
    const int* dst = ei + E;

    float *agg, *h1, *h2;
    int *cnt, *rowptr, *cursor, *bsum;
    int2 *edata;
    cudaGetSymbolAddress((void**)&agg, g_agg);
    cudaGetSymbolAddress((void**)&h1, g_h1);
    cudaGetSymbolAddress((void**)&h2, g_h2);
    cudaGetSymbolAddress((void**)&cnt, g_cnt);
    cudaGetSymbolAddress((void**)&rowptr, g_rowptr);
    cudaGetSymbolAddress((void**)&cursor, g_cursor);
    cudaGetSymbolAddress((void**)&bsum, g_bsum);
    cudaGetSymbolAddress((void**)&edata, g_edata);

    size_t smP  = smem_presplit64();
    size_t sm128 = smem_otf(128);
    cudaFuncSetAttribute(mlp_tc64_kernel<true>,  cudaFuncAttributeMaxDynamicSharedMemorySize, (int)smP);
    cudaFuncSetAttribute(mlp_tc64_kernel<false>, cudaFuncAttributeMaxDynamicSharedMemorySize, (int)smP);
    cudaFuncSetAttribute(mlp_tc_kernel<128, true>, cudaFuncAttributeMaxDynamicSharedMemorySize, (int)sm128);

    int NB = (N + 255) / 256;                // scan blocks (<=512 required)
    int eb = (E + 255) / 256;
    int gb = (N * 16 + 255) / 256;
    int mb = (N + 63) / 64;

    // --- CSR build (by destination) ---
    zero_cnt_kernel<<<NB, 256>>>(cnt, N);
    hist_kernel<<<eb, 256>>>(dst, cnt, E);
    scan_partial_kernel<<<NB, 256>>>(cnt, bsum, N);
    scan_top_kernel<<<1, 32>>>(bsum, NB);
    scan_final_kernel<<<NB + 1, 256>>>(cnt, bsum, rowptr, cursor, N);
    fill_kernel<<<eb, 256>>>(src, dst, ew, cursor, edata, E);

    // --- Layer 1: 64 -> 64 -> 64, relu (pre-split) ---
    gather_kernel<<<gb, 256>>>((const float4*)x, rowptr, edata, (float4*)agg, N);
    mlp_tc64_kernel<true><<<mb, 256, smP>>>((const float4*)agg, w11, b11, w12, b12, h1, N);

    // --- Layer 2: 64 -> 128 -> 64, relu (on-the-fly split) ---
    gather_kernel<<<gb, 256>>>((const float4*)h1, rowptr, edata, (float4*)agg, N);
    mlp_tc_kernel<128, true><<<mb, 256, sm128>>>((const float4*)agg, w21, b21, w22, b22, h2, N);

    // --- Layer 3: 64 -> 64 -> 64, no relu (pre-split) ---
    gather_kernel<<<gb, 256>>>((const float4*)h2, rowptr, edata, (float4*)agg, N);
    mlp_tc64_kernel<false><<<mb, 256, smP>>>((const float4*)agg, w31, b31, w32, b32, out, N);
}

// round 13
// speedup vs baseline: 1.1441x; 1.0623x over previous
#include <cuda_runtime.h>
#include <cuda_bf16.h>
#include <cstdint>

// Problem constants (reference: N=100000, E=1000000, D=64)
#define MAXN 100000
#define MAXE 1000000
#define DIMF 64

// Scratch (device globals; no allocation allowed)
__device__ float g_agg[MAXN * DIMF];
__device__ float g_h1[MAXN * DIMF];
__device__ float g_h2[MAXN * DIMF];
__device__ int   g_cnt[MAXN];
__device__ int   g_rowptr[MAXN + 1];
__device__ int   g_cursor[MAXN];
__device__ int2  g_edata[MAXE];          // {src, float_bits(w)} grouped by dst
__device__ int   g_bsum[512];

// ---------------------------------------------------------------------------
// TF32 helpers
// ---------------------------------------------------------------------------
__device__ __forceinline__ uint32_t f2tf(float a) {
    uint32_t r; asm("cvt.rna.tf32.f32 %0, %1;" : "=r"(r) : "f"(a)); return r;
}
__device__ __forceinline__ void tf_split(float a, uint32_t& hi, uint32_t& lo) {
    hi = f2tf(a);
    lo = f2tf(a - __uint_as_float(hi));
}
__device__ __forceinline__ void mma_tf32(float c[4],
                                         uint32_t a0, uint32_t a1, uint32_t a2, uint32_t a3,
                                         uint32_t b0, uint32_t b1) {
    asm volatile(
        "mma.sync.aligned.m16n8k8.row.col.f32.tf32.tf32.f32 "
        "{%0,%1,%2,%3}, {%4,%5,%6,%7}, {%8,%9}, {%0,%1,%2,%3};"
        : "+f"(c[0]), "+f"(c[1]), "+f"(c[2]), "+f"(c[3])
        : "r"(a0), "r"(a1), "r"(a2), "r"(a3), "r"(b0), "r"(b1));
}

// ---------------------------------------------------------------------------
// CSR build: histogram -> exclusive scan -> fill
// ---------------------------------------------------------------------------
__global__ void zero_cnt_kernel(int* __restrict__ cnt, int N) {
    int i = blockIdx.x * blockDim.x + threadIdx.x;
    if (i < N) cnt[i] = 0;
}

__global__ void hist_kernel(const int* __restrict__ dst, int* __restrict__ cnt, int E) {
    int e = blockIdx.x * blockDim.x + threadIdx.x;
    if (e < E) atomicAdd(&cnt[dst[e]], 1);
}

__global__ void scan_partial_kernel(const int* __restrict__ cnt, int* __restrict__ bsum, int N) {
    __shared__ int sm[256];
    int i = blockIdx.x * 256 + threadIdx.x;
    sm[threadIdx.x] = (i < N) ? cnt[i] : 0;
    __syncthreads();
    for (int s = 128; s > 0; s >>= 1) {
        if (threadIdx.x < s) sm[threadIdx.x] += sm[threadIdx.x + s];
        __syncthreads();
    }
    if (threadIdx.x == 0) bsum[blockIdx.x] = sm[0];
}

__global__ void scan_top_kernel(int* __restrict__ bsum, int NB) {
    int lane = threadIdx.x;          // 32 threads
    int carry = 0;
    for (int base = 0; base < NB; base += 32) {
        int i = base + lane;
        int v = (i < NB) ? bsum[i] : 0;
        int s = v;
        #pragma unroll
        for (int d = 1; d < 32; d <<= 1) {
            int t = __shfl_up_sync(0xFFFFFFFFu, s, d);
            if (lane >= d) s += t;
        }
        if (i < NB) bsum[i] = carry + s - v;   // exclusive
        carry += __shfl_sync(0xFFFFFFFFu, s, 31);
    }
}

__global__ void scan_final_kernel(const int* __restrict__ cnt,
                                  const int* __restrict__ bsum,
                                  int* __restrict__ rowptr,
                                  int* __restrict__ cursor, int N) {
    __shared__ int sm[256];
    int t = threadIdx.x;
    int i = blockIdx.x * 256 + t;
    int v = (i < N) ? cnt[i] : 0;
    sm[t] = v;
    __syncthreads();
    for (int s = 1; s < 256; s <<= 1) {
        int add = (t >= s) ? sm[t - s] : 0;
        __syncthreads();
        sm[t] += add;
        __syncthreads();
    }
    int val = bsum[blockIdx.x] + sm[t] - v;   // exclusive prefix
    if (i < N) {
        rowptr[i] = val;
        cursor[i] = val;
    } else if (i == N) {
        rowptr[N] = val;                      // == E
    }
}

__global__ void fill_kernel(const int* __restrict__ src, const int* __restrict__ dst,
                            const float* __restrict__ ew,
                            int* __restrict__ cursor, int2* __restrict__ edata, int E) {
    int e = blockIdx.x * blockDim.x + threadIdx.x;
    if (e >= E) return;
    int d = dst[e];
    int p = atomicAdd(&cursor[d], 1);
    edata[p] = make_int2(src[e], __float_as_int(ew[e]));
}

// ---------------------------------------------------------------------------
// Gather-aggregate: agg[n] = x[n] + sum_{e in csr(n)} x[src_e] * w_e
// (unchanged R6/R7 winner)
// ---------------------------------------------------------------------------
__global__ void gather_kernel(const float4* __restrict__ x4,
                              const int* __restrict__ rowptr,
                              const int2* __restrict__ edata,
                              float4* __restrict__ agg, int N) {
    int idx = blockIdx.x * blockDim.x + threadIdx.x;
    int n = idx >> 4;
    if (n >= N) return;
    int c = idx & 15;
    unsigned gmask = 0xFFFFu << (threadIdx.x & 16);   // this 16-lane group

    int beg = __ldg(rowptr + n);
    int end = __ldg(rowptr + n + 1);
    float4 acc = x4[(size_t)n * 16 + c];    // GIN identity term

    for (int base = beg; base < end; base += 16) {
        int e = base + c;
        int2 ed = (e < end) ? __ldg(edata + e) : make_int2(0, 0);
        #pragma unroll
        for (int i = 0; i < 16; i++) {
            int s   = __shfl_sync(gmask, ed.x, i, 16);
            float w = __int_as_float(__shfl_sync(gmask, ed.y, i, 16));
            float4 v = __ldg(&x4[(size_t)s * 16 + c]);
            acc.x += v.x * w; acc.y += v.y * w;
            acc.z += v.z * w; acc.w += v.w * w;
        }
    }
    agg[(size_t)n * 16 + c] = acc;
}

// ---------------------------------------------------------------------------
// TF32 MLP for H=64, TR=128 (256 threads, 2 blocks/SM; smem 72.2KB).
// On-the-fly hi/lo split (R10 math, proven), 8 warps = 8 m-tiles, each warp
// covers the full n=64 (8 n-tiles). Halves per-row weight-staging cost and
// block count vs TR=64. hid overlays in_s exactly (both 128x68).
// ---------------------------------------------------------------------------
template<bool RELU_OUT>
__global__ void __launch_bounds__(256, 2) mlp_tc64w_kernel(
        const float4* __restrict__ agg4,
        const float* __restrict__ w1, const float* __restrict__ b1,
        const float* __restrict__ w2, const float* __restrict__ b2,
        float* __restrict__ out, int N) {
    constexpr int TR  = 128;
    constexpr int INS = 68;         // ==4 mod 32 (A-side conflict-free)
    constexpr int WS  = 72;         // ==8 mod 32 (B-side conflict-free)
    constexpr int IN_SZ = TR * INS; // 8704
    constexpr int W_SZ  = 64 * WS;  // 4608

    extern __shared__ float sm[];
    float* in_s = sm;                      // [128][68]
    float* w1n  = sm + IN_SZ;              // [64][72]
    float* hid  = sm;                      // [128][68] overlays in_s
    float* w2n  = w1n + W_SZ;              // [64][72]
    float* b1s  = w2n + W_SZ;              // 64
    float* b2s  = b1s + 64;                // 64

    int tid  = threadIdx.x;
    int row0 = blockIdx.x * TR;
    int nrows = N - row0; if (nrows > TR) nrows = TR;

    // Stage weights (natural [k][n], padded stride) + biases
    for (int i = tid; i < 64 * 64; i += 256) {
        int k = i >> 6, n = i & 63;
        w1n[k * WS + n] = w1[i];
        w2n[k * WS + n] = w2[i];
    }
    if (tid < 64) b1s[tid] = b1[tid];
    else if (tid < 128) b2s[tid - 64] = b2[tid - 64];

    // Stage input tile (zero-pad tail rows)
    for (int i = tid; i < TR * 16; i += 256) {
        int r = i >> 4, k4 = i & 15;
        float4 v = make_float4(0.f, 0.f, 0.f, 0.f);
        if (r < nrows) v = agg4[(size_t)(row0 + r) * 16 + k4];
        *(float4*)(in_s + r * INS + k4 * 4) = v;
    }
    __syncthreads();

    const int wid  = tid >> 5;
    const int lane = tid & 31;
    const int g    = lane >> 2;
    const int tg   = lane & 3;
    const int m0   = wid * 16;      // 8 warps x 16 rows = 128

    // ---- GEMM1: hid = relu(in @ W1 + b1) ----
    float c1[8][4];
    #pragma unroll
    for (int j = 0; j < 8; j++) {
        int n0 = j * 8;
        float bv0 = b1s[n0 + 2 * tg], bv1 = b1s[n0 + 2 * tg + 1];
        c1[j][0] = bv0; c1[j][1] = bv1; c1[j][2] = bv0; c1[j][3] = bv1;
    }
    #pragma unroll
    for (int kk = 0; kk < 8; kk++) {
        int k0 = kk * 8;
        uint32_t ah[4], al[4];
        tf_split(in_s[(m0 + g)     * INS + k0 + tg],     ah[0], al[0]);
        tf_split(in_s[(m0 + g + 8) * INS + k0 + tg],     ah[1], al[1]);
        tf_split(in_s[(m0 + g)     * INS + k0 + tg + 4], ah[2], al[2]);
        tf_split(in_s[(m0 + g + 8) * INS + k0 + tg + 4], ah[3], al[3]);
        #pragma unroll
        for (int j = 0; j < 8; j++) {
            int n0 = j * 8;
            uint32_t bh0, bl0, bh1, bl1;
            tf_split(w1n[(k0 + tg)     * WS + n0 + g], bh0, bl0);
            tf_split(w1n[(k0 + tg + 4) * WS + n0 + g], bh1, bl1);
            mma_tf32(c1[j], ah[0], ah[1], ah[2], ah[3], bh0, bh1);
            mma_tf32(c1[j], ah[0], ah[1], ah[2], ah[3], bl0, bl1);
            mma_tf32(c1[j], al[0], al[1], al[2], al[3], bh0, bh1);
        }
    }
    __syncthreads();   // all reads of in_s done

    // Write relu(hid) (overlays in_s)
    #pragma unroll
    for (int j = 0; j < 8; j++) {
        int n0 = j * 8 + 2 * tg;
        *(float2*)(hid + (m0 + g)     * INS + n0) =
            make_float2(fmaxf(c1[j][0], 0.f), fmaxf(c1[j][1], 0.f));
        *(float2*)(hid + (m0 + g + 8) * INS + n0) =
            make_float2(fmaxf(c1[j][2], 0.f), fmaxf(c1[j][3], 0.f));
    }
    __syncthreads();

    // ---- GEMM2: out = hid @ W2 + b2 ----
    {
        float c2[8][4];
        #pragma unroll
        for (int j = 0; j < 8; j++) {
            int n0 = j * 8;
            float bv0 = b2s[n0 + 2 * tg], bv1 = b2s[n0 + 2 * tg + 1];
            c2[j][0] = bv0; c2[j][1] = bv1; c2[j][2] = bv0; c2[j][3] = bv1;
        }
        #pragma unroll
        for (int kk = 0; kk < 8; kk++) {
            int k0 = kk * 8;
            uint32_t ah[4], al[4];
            tf_split(hid[(m0 + g)     * INS + k0 + tg],     ah[0], al[0]);
            tf_split(hid[(m0 + g + 8) * INS + k0 + tg],     ah[1], al[1]);
            tf_split(hid[(m0 + g)     * INS + k0 + tg + 4], ah[2], al[2]);
            tf_split(hid[(m0 + g + 8) * INS + k0 + tg + 4], ah[3], al[3]);
            #pragma unroll
            for (int j = 0; j < 8; j++) {
                int n0 = j * 8;
                uint32_t bh0, bl0, bh1, bl1;
                tf_split(w2n[(k0 + tg)     * WS + n0 + g], bh0, bl0);
                tf_split(w2n[(k0 + tg + 4) * WS + n0 + g], bh1, bl1);
                mma_tf32(c2[j], ah[0], ah[1], ah[2], ah[3], bh0, bh1);
                mma_tf32(c2[j], ah[0], ah[1], ah[2], ah[3], bl0, bl1);
                mma_tf32(c2[j], al[0], al[1], al[2], al[3], bh0, bh1);
            }
        }
        int r0 = m0 + g, r1 = m0 + g + 8;
        #pragma unroll
        for (int j = 0; j < 8; j++) {
            int n0 = j * 8 + 2 * tg;
            if (r0 < nrows) {
                float2 v = make_float2(c2[j][0], c2[j][1]);
                if (RELU_OUT) { v.x = fmaxf(v.x, 0.f); v.y = fmaxf(v.y, 0.f); }
                *(float2*)(out + (size_t)(row0 + r0) * 64 + n0) = v;
            }
            if (r1 < nrows) {
                float2 v = make_float2(c2[j][2], c2[j][3]);
                if (RELU_OUT) { v.x = fmaxf(v.x, 0.f); v.y = fmaxf(v.y, 0.f); }
                *(float2*)(out + (size_t)(row0 + r1) * 64 + n0) = v;
            }
        }
    }
}

// ---------------------------------------------------------------------------
// On-the-fly split TF32 MLP (R10 winner, byte-for-byte) -- used for H=128.
// ---------------------------------------------------------------------------
template<int H, bool RELU_OUT>
__global__ void __launch_bounds__(256, 2) mlp_tc_kernel(
        const float4* __restrict__ agg4,
        const float* __restrict__ w1, const float* __restrict__ b1,
        const float* __restrict__ w2, const float* __restrict__ b2,
        float* __restrict__ out, int N) {
    constexpr int TR   = 64;
    constexpr int INS  = 68;
    constexpr int W1S  = H + 8;
    constexpr int HS   = H + 4;
    constexpr int W2S  = 72;
    constexpr int IN_SZ = TR * INS;
    constexpr int W1_SZ = 64 * W1S;
    constexpr int NT1  = H / 16;
    constexpr int KS2  = H / 8;

    extern __shared__ float sm[];
    float* in_s = sm;
    float* w1n  = sm + IN_SZ;
    float* hid  = sm;
    float* w2n  = sm + IN_SZ + W1_SZ;
    float* b1s  = w2n + H * W2S;
    float* b2s  = b1s + H;
    static_assert(TR * HS <= IN_SZ + W1_SZ, "hid overlay must fit");

    int tid  = threadIdx.x;
    int row0 = blockIdx.x * TR;
    int nrows = N - row0; if (nrows > TR) nrows = TR;

    for (int i = tid; i < 64 * H; i += 256) {
        int k = i / H, n = i % H;
        w1n[k * W1S + n] = w1[i];
    }
    for (int i = tid; i < H * 64; i += 256) {
        int h = i / 64, n = i % 64;
        w2n[h * W2S + n] = w2[i];
    }
    if (tid < H)  b1s[tid] = b1[tid];
    if (tid < 64) b2s[tid] = b2[tid];

    for (int i = tid; i < TR * 16; i += 256) {
        int r = i >> 4, k4 = i & 15;
        float4 v = make_float4(0.f, 0.f, 0.f, 0.f);
        if (r < nrows) v = agg4[(size_t)(row0 + r) * 16 + k4];
        *(float4*)(in_s + r * INS + k4 * 4) = v;
    }
    __syncthreads();

    const int wid  = tid >> 5;
    const int lane = tid & 31;
    const int g    = lane >> 2;
    const int tg   = lane & 3;
    const int m0   = (wid >> 1) * 16;
    const int nb1  = (wid & 1) * NT1 * 8;

    float c1[NT1][4];
    #pragma unroll
    for (int j = 0; j < NT1; j++) {
        int n0 = nb1 + j * 8;
        float bv0 = b1s[n0 + 2 * tg], bv1 = b1s[n0 + 2 * tg + 1];
        c1[j][0] = bv0; c1[j][1] = bv1; c1[j][2] = bv0; c1[j][3] = bv1;
    }
    #pragma unroll
    for (int kk = 0; kk < 8; kk++) {
        int k0 = kk * 8;
        uint32_t ah[4], al[4];
        tf_split(in_s[(m0 + g)     * INS + k0 + tg],     ah[0], al[0]);
        tf_split(in_s[(m0 + g + 8) * INS + k0 + tg],     ah[1], al[1]);
        tf_split(in_s[(m0 + g)     * INS + k0 + tg + 4], ah[2], al[2]);
        tf_split(in_s[(m0 + g + 8) * INS + k0 + tg + 4], ah[3], al[3]);
        #pragma unroll
        for (int j = 0; j < NT1; j++) {
            int n0 = nb1 + j * 8;
            uint32_t bh0, bl0, bh1, bl1;
            tf_split(w1n[(k0 + tg)     * W1S + n0 + g], bh0, bl0);
            tf_split(w1n[(k0 + tg + 4) * W1S + n0 + g], bh1, bl1);
            mma_tf32(c1[j], ah[0], ah[1], ah[2], ah[3], bh0, bh1);
            mma_tf32(c1[j], ah[0], ah[1], ah[2], ah[3], bl0, bl1);
            mma_tf32(c1[j], al[0], al[1], al[2], al[3], bh0, bh1);
        }
    }
    __syncthreads();

    #pragma unroll
    for (int j = 0; j < NT1; j++) {
        int n0 = nb1 + j * 8 + 2 * tg;
        *(float2*)(hid + (m0 + g)     * HS + n0) =
            make_float2(fmaxf(c1[j][0], 0.f), fmaxf(c1[j][1], 0.f));
        *(float2*)(hid + (m0 + g + 8) * HS + n0) =
            make_float2(fmaxf(c1[j][2], 0.f), fmaxf(c1[j][3], 0.f));
    }
    __syncthreads();

    {
        constexpr int NT2 = 4;
        int nb2 = (wid & 1) * 32;
        float c2[NT2][4];
        #pragma unroll
        for (int j = 0; j < NT2; j++) {
            int n0 = nb2 + j * 8;
            float bv0 = b2s[n0 + 2 * tg], bv1 = b2s[n0 + 2 * tg + 1];
            c2[j][0] = bv0; c2[j][1] = bv1; c2[j][2] = bv0; c2[j][3] = bv1;
        }
        #pragma unroll
        for (int kk = 0; kk < KS2; kk++) {
            int k0 = kk * 8;
            uint32_t ah[4], al[4];
            tf_split(hid[(m0 + g)     * HS + k0 + tg],     ah[0], al[0]);
            tf_split(hid[(m0 + g + 8) * HS + k0 + tg],     ah[1], al[1]);
            tf_split(hid[(m0 + g)     * HS + k0 + tg + 4], ah[2], al[2]);
            tf_split(hid[(m0 + g + 8) * HS + k0 + tg + 4], ah[3], al[3]);
            #pragma unroll
            for (int j = 0; j < NT2; j++) {
                int n0 = nb2 + j * 8;
                uint32_t bh0, bl0, bh1, bl1;
                tf_split(w2n[(k0 + tg)     * W2S + n0 + g], bh0, bl0);
                tf_split(w2n[(k0 + tg + 4) * W2S + n0 + g], bh1, bl1);
                mma_tf32(c2[j], ah[0], ah[1], ah[2], ah[3], bh0, bh1);
                mma_tf32(c2[j], ah[0], ah[1], ah[2], ah[3], bl0, bl1);
                mma_tf32(c2[j], al[0], al[1], al[2], al[3], bh0, bh1);
            }
        }
        int r0 = m0 + g, r1 = m0 + g + 8;
        #pragma unroll
        for (int j = 0; j < NT2; j++) {
            int n0 = nb2 + j * 8 + 2 * tg;
            if (r0 < nrows) {
                float2 v = make_float2(c2[j][0], c2[j][1]);
                if (RELU_OUT) { v.x = fmaxf(v.x, 0.f); v.y = fmaxf(v.y, 0.f); }
                *(float2*)(out + (size_t)(row0 + r0) * 64 + n0) = v;
            }
            if (r1 < nrows) {
                float2 v = make_float2(c2[j][2], c2[j][3]);
                if (RELU_OUT) { v.x = fmaxf(v.x, 0.f); v.y = fmaxf(v.y, 0.f); }
                *(float2*)(out + (size_t)(row0 + r1) * 64 + n0) = v;
            }
        }
    }
}

// ---------------------------------------------------------------------------
// Launch
// ---------------------------------------------------------------------------
static inline size_t smem_tc64w() {
    // in(128*68) + w1(64*72) + w2(64*72) + biases(128)
    return (size_t)(128 * 68 + 2 * 64 * 72 + 128) * sizeof(float);
}
static inline size_t smem_otf(int H) {
    size_t floats = (size_t)64 * 68 + (size_t)64 * (H + 8) + (size_t)H * 72 + H + 64;
    return floats * sizeof(float);
}

extern "C" void kernel_launch(void* const* d_in, const int* in_sizes, int n_in,
                              void* d_out, int out_size) {
    const float* x   = (const float*)d_in[0];
    const int*   ei  = (const int*)d_in[1];
    const float* ew  = (const float*)d_in[2];
    const float* w11 = (const float*)d_in[3];
    const float* b11 = (const float*)d_in[4];
    const float* w12 = (const float*)d_in[5];
    const float* b12 = (const float*)d_in[6];
    const float* w21 = (const float*)d_in[7];
    const float* b21 = (const float*)d_in[8];
    const float* w22 = (const float*)d_in[9];
    const float* b22 = (const float*)d_in[10];
    const float* w31 = (const float*)d_in[11];
    const float* b31 = (const float*)d_in[12];
    const float* w32 = (const float*)d_in[13];
    const float* b32 = (const float*)d_in[14];
    float* out = (float*)d_out;

    int N = in_sizes[0] / DIMF;
    int E = in_sizes[1] / 2;
    const int* src = ei;
    const int* dst = ei + E;

    float *agg, *h1, *h2;
    int *cnt, *rowptr, *cursor, *bsum;
    int2 *edata;
    cudaGetSymbolAddress((void**)&agg, g_agg);
    cudaGetSymbolAddress((void**)&h1, g_h1);
    cudaGetSymbolAddress((void**)&h2, g_h2);
    cudaGetSymbolAddress((void**)&cnt, g_cnt);
    cudaGetSymbolAddress((void**)&rowptr, g_rowptr);
    cudaGetSymbolAddress((void**)&cursor, g_cursor);
    cudaGetSymbolAddress((void**)&bsum, g_bsum);
    cudaGetSymbolAddress((void**)&edata, g_edata);

    size_t smW  = smem_tc64w();
    size_t sm128 = smem_otf(128);
    cudaFuncSetAttribute(mlp_tc64w_kernel<true>,  cudaFuncAttributeMaxDynamicSharedMemorySize, (int)smW);
    cudaFuncSetAttribute(mlp_tc64w_kernel<false>, cudaFuncAttributeMaxDynamicSharedMemorySize, (int)smW);
    cudaFuncSetAttribute(mlp_tc_kernel<128, true>, cudaFuncAttributeMaxDynamicSharedMemorySize, (int)sm128);

    int NB = (N + 255) / 256;                // scan blocks (<=512 required)
    int eb = (E + 255) / 256;
    int gb = (N * 16 + 255) / 256;
    int mb64  = (N + 127) / 128;
    int mb128 = (N + 63) / 64;

    // --- CSR build (by destination) ---
    zero_cnt_kernel<<<NB, 256>>>(cnt, N);
    hist_kernel<<<eb, 256>>>(dst, cnt, E);
    scan_partial_kernel<<<NB, 256>>>(cnt, bsum, N);
    scan_top_kernel<<<1, 32>>>(bsum, NB);
    scan_final_kernel<<<NB + 1, 256>>>(cnt, bsum, rowptr, cursor, N);
    fill_kernel<<<eb, 256>>>(src, dst, ew, cursor, edata, E);

    // --- Layer 1: 64 -> 64 -> 64, relu (TR=128) ---
    gather_kernel<<<gb, 256>>>((const float4*)x, rowptr, edata, (float4*)agg, N);
    mlp_tc64w_kernel<true><<<mb64, 256, smW>>>((const float4*)agg, w11, b11, w12, b12, h1, N);

    // --- Layer 2: 64 -> 128 -> 64, relu (R10 kernel) ---
    gather_kernel<<<gb, 256>>>((const float4*)h1, rowptr, edata, (float4*)agg, N);
    mlp_tc_kernel<128, true><<<mb128, 256, sm128>>>((const float4*)agg, w21, b21, w22, b22, h2, N);

    // --- Layer 3: 64 -> 64 -> 64, no relu (TR=128) ---
    gather_kernel<<<gb, 256>>>((const float4*)h2, rowptr, edata, (float4*)agg, N);
    mlp_tc64w_kernel<false><<<mb64, 256, smW>>>((const float4*)agg, w31, b31, w32, b32, out, N);
}